// round 9
// baseline (speedup 1.0000x reference)
#include <cuda_runtime.h>
#include <math.h>

#define HH 256
#define WW 320
#define CCH 28
#define HWSZ (HH*WW)          // 81920
#define NB 2
#define NELEM (NB*CCH*HWSZ)   // 4587520
#define NPIX (NB*HWSZ)        // 163840

// ---------------- scratch (static device globals) -----------------------------
__device__ float g_xn[NELEM];     // NCHW input; later pw1 out; later xo (split rows)
__device__ float g_tmp[NELEM];    // gemm outputs (pass1 tmp / pass3 y / pass4 y2)
__device__ float g_b1[NELEM];     // butterfly buffer
__device__ float g_xdct[NELEM];
__device__ float g_xlow[NELEM];
__device__ float g_xconv[NELEM];
__device__ float g_loc[NELEM];
__device__ float g_gqk[8*784];
__device__ float g_wvp[8*784];
// even/odd packed DCT matrices
__device__ float g_DHp[2*128*128];
__device__ float g_DWp[2*160*160];
__device__ float g_DIHp[2*128*128];
__device__ float g_DIWp[2*160*160];

__device__ __forceinline__ float gelu_f(float x){
    return 0.5f*x*(1.0f + erff(x*0.7071067811865476f));
}

// ---------------- packed DCT matrix fills --------------------------------------
__global__ void fill_DHp(float* D){     // D[p][k'][h'] = DH[2k'+p][h'], N=256
    int i = blockIdx.x*blockDim.x + threadIdx.x;
    if (i < 2*128*128){
        int p = i / 16384, r = i % 16384;
        int k2 = r / 128, h = r % 128;
        int k = 2*k2 + p;
        int rr = ((2*h+1)*k) % 1024;
        D[i] = 2.0f * cospif((float)rr / 512.0f);
    }
}
__global__ void fill_DWp(float* D){     // D[p][l'][w'] = DW[2l'+p][w'], N=320
    int i = blockIdx.x*blockDim.x + threadIdx.x;
    if (i < 2*160*160){
        int p = i / 25600, r = i % 25600;
        int l2 = r / 160, w = r % 160;
        int k = 2*l2 + p;
        int rr = ((2*w+1)*k) % 1280;
        D[i] = 2.0f * cospif((float)rr / 640.0f);
    }
}
__global__ void fill_DIHp(float* D){    // D[p][n'][k'] = DIH[n'][2k'+p], N=256
    int i = blockIdx.x*blockDim.x + threadIdx.x;
    if (i < 2*128*128){
        int p = i / 16384, r = i % 16384;
        int n = r / 128, k2 = r % 128;
        int k = 2*k2 + p;
        if (k == 0) D[i] = 1.0f/512.0f;
        else {
            int rr = ((2*n+1)*k) % 1024;
            D[i] = cospif((float)rr / 512.0f) / 256.0f;
        }
    }
}
__global__ void fill_DIWp(float* D){    // D[p][n'][l'] = DIW[n'][2l'+p], N=320
    int i = blockIdx.x*blockDim.x + threadIdx.x;
    if (i < 2*160*160){
        int p = i / 25600, r = i % 25600;
        int n = r / 160, k2 = r % 160;
        int k = 2*k2 + p;
        if (k == 0) D[i] = 1.0f/640.0f;
        else {
            int rr = ((2*n+1)*k) % 1280;
            D[i] = cospif((float)rr / 640.0f) / 320.0f;
        }
    }
}

// ---------------- NHWC -> NCHW transpose ---------------------------------------
__global__ __launch_bounds__(256) void transpose_in(const float* __restrict__ x){
    __shared__ float s[32*28];
    int blk = blockIdx.x;
    int b   = blk / (HWSZ/32);
    int hw0 = (blk % (HWSZ/32)) * 32;
    const float* src = x + ((long)b*HWSZ + hw0)*CCH;
    for (int idx = threadIdx.x; idx < 32*CCH; idx += blockDim.x) s[idx] = src[idx];
    __syncthreads();
    for (int idx = threadIdx.x; idx < 32*CCH; idx += blockDim.x){
        int c = idx / 32, i = idx % 32;
        g_xn[((long)b*CCH + c)*HWSZ + hw0 + i] = s[i*CCH + c];
    }
}

// ---------------- butterflies --------------------------------------------------
// rows h' & 255-h' of xn -> b1 rows h' (sum) / 128+h' (diff)
__global__ __launch_bounds__(256) void bf_h(void){
    int idx = blockIdx.x*256 + threadIdx.x;            // 56*128*320
    int bc = idx / (128*320);
    int r  = idx % (128*320);
    int h = r / 320, w = r % 320;
    long base = (long)bc*HWSZ;
    float a = g_xn[base + (long)h*320 + w];
    float b = g_xn[base + (long)(255-h)*320 + w];
    g_b1[base + (long)h*320 + w]        = a + b;
    g_b1[base + (long)(128+h)*320 + w]  = a - b;
}
// cols w' & 319-w' of tmp -> b1 cols w' (sum) / 160+w' (diff)
__global__ __launch_bounds__(256) void bf_w(void){
    int idx = blockIdx.x*256 + threadIdx.x;            // 56*256*160
    int bc = idx / (256*160);
    int r  = idx % (256*160);
    int k = r / 160, w = r % 160;
    long base = (long)bc*HWSZ + (long)k*320;
    float a = g_tmp[base + w];
    float b = g_tmp[base + 319 - w];
    g_b1[base + w]       = a + b;
    g_b1[base + 160 + w] = a - b;
}
// yE/yO (tmp rows 0-127 / 128-255) -> t2 parity-split cols into b1
__global__ __launch_bounds__(256) void bf_mid(void){
    int idx = blockIdx.x*256 + threadIdx.x;            // 56*128*320
    int bc = idx / (128*320);
    int r  = idx % (128*320);
    int n = r / 320, l = r % 320;
    long base = (long)bc*HWSZ;
    float e = g_tmp[base + (long)n*320 + l];
    float o = g_tmp[base + (long)(128+n)*320 + l];
    int col = (l >> 1) + (l & 1)*160;
    g_b1[base + (long)n*320 + col]        = e + o;
    g_b1[base + (long)(255-n)*320 + col]  = e - o;
}

// ---------------- half-K GEMMs -------------------------------------------------
// gemm_n: C[m,n] = sum_k A[m,k]*B[k,n].  M=128 (y=2), N=320 (x=5), 64x64 tiles.
// z = bc*2+p. Output row stride crs, parity offset sCp.
__global__ __launch_bounds__(256) void gemm_n(
    const float* __restrict__ A, int lda, long sAp,
    const float* __restrict__ B, int ldb, long sBbc, long sBp,
    float* __restrict__ C, int ldc, long sCbc, long sCp, int crs, int Kd)
{
    __shared__ float As[16][64];
    __shared__ float Bs[16][64];
    int z = blockIdx.z;
    int bc = z >> 1, p = z & 1;
    A += (long)p*sAp;
    B += (long)bc*sBbc + (long)p*sBp;
    C += (long)bc*sCbc + (long)p*sCp;
    int m0 = blockIdx.y*64, n0 = blockIdx.x*64;
    int t = threadIdx.x;
    int tx = t & 15, ty = t >> 4;
    float acc[4][4];
#pragma unroll
    for (int i=0;i<4;i++)
#pragma unroll
        for (int j=0;j<4;j++) acc[i][j] = 0.f;

    for (int k0 = 0; k0 < Kd; k0 += 16){
        {
            int r = t >> 2, cc = (t & 3) << 2;
            float4 a4 = *reinterpret_cast<const float4*>(A + (long)(m0+r)*lda + k0 + cc);
            As[cc+0][r]=a4.x; As[cc+1][r]=a4.y; As[cc+2][r]=a4.z; As[cc+3][r]=a4.w;
        }
        {
            int r = t >> 4, cc = (t & 15) << 2;
            float4 b4 = *reinterpret_cast<const float4*>(B + (long)(k0+r)*ldb + n0 + cc);
            *reinterpret_cast<float4*>(&Bs[r][cc]) = b4;
        }
        __syncthreads();
#pragma unroll
        for (int kk=0; kk<16; kk++){
            float4 a4 = *reinterpret_cast<float4*>(&As[kk][ty<<2]);
            float4 b4 = *reinterpret_cast<float4*>(&Bs[kk][tx<<2]);
            float av[4] = {a4.x,a4.y,a4.z,a4.w};
            float bv[4] = {b4.x,b4.y,b4.z,b4.w};
#pragma unroll
            for (int i=0;i<4;i++)
#pragma unroll
                for (int j=0;j<4;j++) acc[i][j] += av[i]*bv[j];
        }
        __syncthreads();
    }
#pragma unroll
    for (int i=0;i<4;i++){
        float4 r4 = make_float4(acc[i][0],acc[i][1],acc[i][2],acc[i][3]);
        long row = (long)(m0+(ty<<2)+i)*crs;
        *reinterpret_cast<float4*>(C + row*ldc + n0 + (tx<<2)) = r4;
    }
}

// gemm_t: C[m,n] = sum_k A[m,k]*B[n,k].  M (y blocks of 64), N=160 (x=5, 32-tiles).
// Output col stride ccs, parity offset sCp.
__global__ __launch_bounds__(256) void gemm_t(
    const float* __restrict__ A, int lda, long sAbc, long sAp,
    const float* __restrict__ B, int ldb, long sBp,
    float* __restrict__ C, int ldc, long sCbc, long sCp, int ccs, int Kd)
{
    __shared__ float As[16][64];
    __shared__ float Bs[16][32];
    int z = blockIdx.z;
    int bc = z >> 1, p = z & 1;
    A += (long)bc*sAbc + (long)p*sAp;
    B += (long)p*sBp;
    C += (long)bc*sCbc + (long)p*sCp;
    int m0 = blockIdx.y*64, n0 = blockIdx.x*32;
    int t = threadIdx.x;
    int tx = t & 7, ty = t >> 3;   // 8 col-groups x 32 row-groups
    float acc[2][4];
#pragma unroll
    for (int i=0;i<2;i++)
#pragma unroll
        for (int j=0;j<4;j++) acc[i][j] = 0.f;

    for (int k0 = 0; k0 < Kd; k0 += 16){
        {
            int r = t >> 2, cc = (t & 3) << 2;
            float4 a4 = *reinterpret_cast<const float4*>(A + (long)(m0+r)*lda + k0 + cc);
            As[cc+0][r]=a4.x; As[cc+1][r]=a4.y; As[cc+2][r]=a4.z; As[cc+3][r]=a4.w;
        }
        if (t < 128){
            int r = t >> 2, cc = (t & 3) << 2;
            float4 b4 = *reinterpret_cast<const float4*>(B + (long)(n0+r)*ldb + k0 + cc);
            Bs[cc+0][r]=b4.x; Bs[cc+1][r]=b4.y; Bs[cc+2][r]=b4.z; Bs[cc+3][r]=b4.w;
        }
        __syncthreads();
#pragma unroll
        for (int kk=0; kk<16; kk++){
            float2 a2 = *reinterpret_cast<float2*>(&As[kk][ty<<1]);
            float4 b4 = *reinterpret_cast<float4*>(&Bs[kk][tx<<2]);
            float av[2] = {a2.x, a2.y};
            float bv[4] = {b4.x,b4.y,b4.z,b4.w};
#pragma unroll
            for (int i=0;i<2;i++)
#pragma unroll
                for (int j=0;j<4;j++) acc[i][j] += av[i]*bv[j];
        }
        __syncthreads();
    }
#pragma unroll
    for (int i=0;i<2;i++)
#pragma unroll
        for (int j=0;j<4;j++){
            long row = (long)(m0+(ty<<1)+i);
            C[row*ldc + (long)(n0+(tx<<2)+j)*ccs] = acc[i][j];
        }
}

// ---------------- spectral attention (R5-verified) -----------------------------
__global__ __launch_bounds__(256) void spec_attn_kernel(
    const float* __restrict__ wq, const float* __restrict__ wk,
    const float* __restrict__ wv, const float* __restrict__ rescale,
    const float* __restrict__ pw, const float* __restrict__ pb)
{
    __shared__ float X[64*29];
    __shared__ float qs[28*65], ks[28*65];
    __shared__ float attn[28*29];
    __shared__ float wqs[784], wks[784], wvs[784], pws[784];
    __shared__ float U[784], Macc[784];
    __shared__ float invq[28], invk[28];

    int blk = blockIdx.x;
    int b = blk / 1280;
    int n = blk % 1280;
    int ph = n / 40, pwi = n % 40;
    int t = threadIdx.x;
    long base = (long)b*CCH*HWSZ + (long)ph*8*WW + pwi*8;

    for (int idx = t; idx < 1792; idx += 256){
        int c = idx >> 6, m = idx & 63;
        X[m*29 + c] = g_xdct[base + (long)c*HWSZ + (m>>3)*WW + (m&7)];
    }
    for (int idx = t; idx < 784; idx += 256) Macc[idx] = 0.f;

    for (int h = 0; h < 8; h++){
        __syncthreads();
        for (int idx = t; idx < 784; idx += 256){
            int c = idx / 28, d = idx % 28;
            int col = h*28 + d;
            wqs[idx] = wq[c*224 + col];
            wks[idx] = wk[c*224 + col];
            wvs[idx] = wv[c*224 + col];
            pws[d*28 + c] = pw[col*28 + c];
        }
        __syncthreads();
        if (t < 224){
            int d0 = (t >> 4) * 2;
            int m0 = (t & 15) * 4;
            float aq[2][4], ak[2][4];
#pragma unroll
            for (int i=0;i<2;i++)
#pragma unroll
                for (int j=0;j<4;j++){ aq[i][j]=0.f; ak[i][j]=0.f; }
#pragma unroll 4
            for (int c = 0; c < 28; c++){
                float xv[4];
#pragma unroll
                for (int j=0;j<4;j++) xv[j] = X[(m0+j)*29 + c];
                float w0q = wqs[c*28+d0], w1q = wqs[c*28+d0+1];
                float w0k = wks[c*28+d0], w1k = wks[c*28+d0+1];
#pragma unroll
                for (int j=0;j<4;j++){
                    aq[0][j] += xv[j]*w0q; aq[1][j] += xv[j]*w1q;
                    ak[0][j] += xv[j]*w0k; ak[1][j] += xv[j]*w1k;
                }
            }
#pragma unroll
            for (int i=0;i<2;i++)
#pragma unroll
                for (int j=0;j<4;j++){
                    qs[(d0+i)*65 + m0+j] = aq[i][j];
                    ks[(d0+i)*65 + m0+j] = ak[i][j];
                }
        }
        __syncthreads();
        if (t < 56){
            int d = t % 28;
            float* p2 = (t < 28) ? qs : ks;
            float s = 0.f;
#pragma unroll 8
            for (int m=0;m<64;m++){ float v = p2[d*65+m]; s += v*v; }
            float inv = 1.0f / fmaxf(sqrtf(s), 1e-12f);
            if (t < 28) invq[d] = inv; else invk[d] = inv;
        }
        __syncthreads();
        float rs = rescale[h];
        if (t < 196){
            int d0 = (t / 14) * 2;
            int e0 = (t % 14) * 2;
            float a00=0,a01=0,a10=0,a11=0;
#pragma unroll 8
            for (int m=0;m<64;m++){
                float q0 = qs[d0*65+m], q1 = qs[(d0+1)*65+m];
                float k0 = ks[e0*65+m], k1 = ks[(e0+1)*65+m];
                a00 += q0*k0; a01 += q0*k1; a10 += q1*k0; a11 += q1*k1;
            }
            attn[d0*29 + e0]       = a00*invq[d0]  *invk[e0]  *rs;
            attn[d0*29 + e0+1]     = a01*invq[d0]  *invk[e0+1]*rs;
            attn[(d0+1)*29 + e0]   = a10*invq[d0+1]*invk[e0]  *rs;
            attn[(d0+1)*29 + e0+1] = a11*invq[d0+1]*invk[e0+1]*rs;
        }
        __syncthreads();
        if (t < 28){
            float* row = attn + t*29;
            float mx = row[0];
#pragma unroll
            for (int e=1;e<28;e++) mx = fmaxf(mx, row[e]);
            float s = 0.f;
#pragma unroll
            for (int e=0;e<28;e++){ float ev = expf(row[e]-mx); row[e]=ev; s += ev; }
            float invs = 1.0f/s;
#pragma unroll
            for (int e=0;e<28;e++) row[e] *= invs;
        }
        __syncthreads();
        for (int idx = t; idx < 784; idx += 256){
            int e = idx / 28, cp = idx % 28;
            float s = 0.f;
#pragma unroll
            for (int d = 0; d < 28; d++) s += attn[d*29+e]*pws[d*28+cp];
            U[idx] = s;
        }
        __syncthreads();
        for (int idx = t; idx < 784; idx += 256){
            int c = idx / 28, cp = idx % 28;
            float s = 0.f;
#pragma unroll
            for (int e = 0; e < 28; e++) s += wvs[c*28+e]*U[e*28+cp];
            Macc[idx] += s;
        }
    }
    __syncthreads();
    for (int idx = t; idx < 1792; idx += 256){
        int m = idx / 28, cp = idx % 28;
        float s = pb[cp];
#pragma unroll
        for (int c = 0; c < 28; c++) s += X[m*29+c]*Macc[c*28+cp];
        g_xlow[base + (long)cp*HWSZ + (m>>3)*WW + (m&7)] = s;
    }
}

// ---------------- local attention fused-weight precompute ----------------------
__global__ void loc_fuse_kernel(const float* __restrict__ wq,
                                const float* __restrict__ wkv,
                                const float* __restrict__ pw)
{
    int idx = blockIdx.x*blockDim.x + threadIdx.x;
    const float qscale = 0.18898223650461363f;
    if (idx < 6272){
        int h = idx / 784, r = idx % 784;
        int c = r / 28, c2 = r % 28;
        float s = 0.f;
#pragma unroll
        for (int d = 0; d < 28; d++)
            s += wq[c*224 + h*28 + d] * wkv[c2*448 + h*28 + d];
        g_gqk[idx] = s * qscale;
    } else if (idx < 12544){
        int i2 = idx - 6272;
        int h = i2 / 784, r = i2 % 784;
        int c = r / 28, cp = r % 28;
        float s = 0.f;
#pragma unroll
        for (int d = 0; d < 28; d++)
            s += wkv[c*448 + 224 + h*28 + d] * pw[(h*28 + d)*28 + cp];
        g_wvp[i2] = s;
    }
}

// ---------------- windowed local attention (R5-verified) -----------------------
__global__ __launch_bounds__(256) void local_attn_kernel(
    const float* __restrict__ x, const float* __restrict__ pos,
    const float* __restrict__ pb)
{
    extern __shared__ float sm[];
    float* X   = sm;
    float* T   = X   + 64*29;
    float* V2  = T   + 64*29;
    float* sim = V2  + 64*29;
    float* oacc= sim + 64*65;
    float* wg  = oacc+ 64*29;
    float* wv2 = wg  + 784;

    int blk = blockIdx.x;
    int b = blk / 1280;
    int n = blk % 1280;
    int ph = n / 40, pwi = n % 40;
    int t = threadIdx.x;
    long basex = (((long)b*HH + ph*8)*WW + pwi*8)*CCH;

    for (int idx = t; idx < 1792; idx += 256){
        int i = idx / 28, c = idx % 28;
        X[i*29 + c] = x[basex + ((i>>3)*WW + (i&7))*CCH + c];
    }
    for (int idx = t; idx < 1792; idx += 256){
        int m = idx / 28, c = idx % 28;
        oacc[m*29 + c] = pb[c];
    }

    for (int h = 0; h < 8; h++){
        __syncthreads();
        for (int idx = t; idx < 784; idx += 256){
            wg[idx]  = g_gqk[h*784 + idx];
            wv2[idx] = g_wvp[h*784 + idx];
        }
        __syncthreads();
        if (t < 224){
            int i0 = (t & 15) * 4;
            int d0 = (t >> 4) * 2;
            float aT[4][2], aV[4][2];
#pragma unroll
            for (int i=0;i<4;i++){ aT[i][0]=aT[i][1]=aV[i][0]=aV[i][1]=0.f; }
#pragma unroll 4
            for (int c=0;c<28;c++){
                float xv[4];
#pragma unroll
                for (int i=0;i<4;i++) xv[i] = X[(i0+i)*29 + c];
                float g0 = wg[c*28+d0],  g1 = wg[c*28+d0+1];
                float v0 = wv2[c*28+d0], v1 = wv2[c*28+d0+1];
#pragma unroll
                for (int i=0;i<4;i++){
                    aT[i][0]+=xv[i]*g0; aT[i][1]+=xv[i]*g1;
                    aV[i][0]+=xv[i]*v0; aV[i][1]+=xv[i]*v1;
                }
            }
#pragma unroll
            for (int i=0;i<4;i++){
                T [(i0+i)*29 + d0]   = aT[i][0];
                T [(i0+i)*29 + d0+1] = aT[i][1];
                V2[(i0+i)*29 + d0]   = aV[i][0];
                V2[(i0+i)*29 + d0+1] = aV[i][1];
            }
        }
        __syncthreads();
        {
            int i0 = (t >> 4) * 4;
            int j0 = (t & 15) * 4;
            float acc[4][4];
#pragma unroll
            for (int i=0;i<4;i++)
#pragma unroll
                for (int j=0;j<4;j++) acc[i][j]=0.f;
#pragma unroll 4
            for (int d=0;d<28;d++){
                float qv[4], kv[4];
#pragma unroll
                for (int i=0;i<4;i++) qv[i] = T[(i0+i)*29 + d];
#pragma unroll
                for (int j=0;j<4;j++) kv[j] = X[(j0+j)*29 + d];
#pragma unroll
                for (int i=0;i<4;i++)
#pragma unroll
                    for (int j=0;j<4;j++) acc[i][j] += qv[i]*kv[j];
            }
            const float* ph2 = pos + h*4096;
#pragma unroll
            for (int i=0;i<4;i++)
#pragma unroll
                for (int j=0;j<4;j++)
                    sim[(i0+i)*65 + j0+j] = acc[i][j] + ph2[(i0+i)*64 + j0+j];
        }
        __syncthreads();
        if (t < 64){
            float* row = sim + t*65;
            float mx = row[0];
#pragma unroll 8
            for (int j=1;j<64;j++) mx = fmaxf(mx, row[j]);
            float s = 0.f;
#pragma unroll 8
            for (int j=0;j<64;j++){ float ev = expf(row[j]-mx); row[j]=ev; s+=ev; }
            float invs = 1.0f/s;
#pragma unroll 8
            for (int j=0;j<64;j++) row[j] *= invs;
        }
        __syncthreads();
        if (t < 224){
            int i0 = (t & 15) * 4;
            int c0 = (t >> 4) * 2;
            float acc[4][2];
#pragma unroll
            for (int i=0;i<4;i++){ acc[i][0]=0.f; acc[i][1]=0.f; }
#pragma unroll 4
            for (int j=0;j<64;j++){
                float v0 = V2[j*29 + c0], v1 = V2[j*29 + c0+1];
                float sv[4];
#pragma unroll
                for (int i=0;i<4;i++) sv[i] = sim[(i0+i)*65 + j];
#pragma unroll
                for (int i=0;i<4;i++){ acc[i][0]+=sv[i]*v0; acc[i][1]+=sv[i]*v1; }
            }
#pragma unroll
            for (int i=0;i<4;i++){
                oacc[(i0+i)*29 + c0]   += acc[i][0];
                oacc[(i0+i)*29 + c0+1] += acc[i][1];
            }
        }
    }
    __syncthreads();
    for (int idx = t; idx < 1792; idx += 256){
        int c = idx >> 6, m = idx & 63;
        g_loc[((long)b*CCH + c)*HWSZ + (ph*8 + (m>>3))*WW + pwi*8 + (m&7)] = oacc[m*29 + c];
    }
}

// ---------------- high-frequency conv path -------------------------------------
__global__ __launch_bounds__(256) void pw1_gelu_kernel(const float* __restrict__ W){
    __shared__ float Ws[784];
    for (int idx = threadIdx.x; idx < 784; idx += 256) Ws[idx] = W[idx];
    __syncthreads();
    int p = blockIdx.x*256 + threadIdx.x;
    int b = p / HWSZ; int hw = p % HWSZ;
    long base = (long)b*CCH*HWSZ + hw;
    float xin[28];
#pragma unroll
    for (int c=0;c<28;c++) xin[c] = g_xdct[base + (long)c*HWSZ];
#pragma unroll 2
    for (int o=0;o<28;o++){
        float s = 0.f;
#pragma unroll
        for (int c=0;c<28;c++) s += Ws[o*28+c]*xin[c];
        g_xn[base + (long)o*HWSZ] = gelu_f(s);
    }
}

__global__ __launch_bounds__(256) void dw_gelu_add_kernel(const float* __restrict__ Wd){
    int id = blockIdx.x*256 + threadIdx.x;
    if (id >= NELEM) return;
    int w = id % WW;
    int r1 = id / WW;
    int h = r1 % HH;
    int bc = r1 / HH;
    int c = bc % CCH;
    float acc = 0.f;
#pragma unroll
    for (int dh=-1; dh<=1; dh++){
        int hy = h + dh;
        if (hy < 0 || hy >= HH) continue;
#pragma unroll
        for (int dw2=-1; dw2<=1; dw2++){
            int wx = w + dw2;
            if (wx < 0 || wx >= WW) continue;
            acc += g_xn[((long)bc*HH + hy)*WW + wx] * Wd[c*9 + (dh+1)*3 + (dw2+1)];
        }
    }
    g_xconv[id] = gelu_f(acc) + g_xdct[id];
}

// combine: writes xo with PARITY-SPLIT ROWS into g_xn:  row = (h&1)*128 + (h>>1)
__global__ __launch_bounds__(256) void combine_kernel(
    const float* __restrict__ W2, const float* __restrict__ coef)
{
    __shared__ float Ws[784];
    for (int idx = threadIdx.x; idx < 784; idx += 256) Ws[idx] = W2[idx];
    __syncthreads();
    int p = blockIdx.x*256 + threadIdx.x;
    int b = p / HWSZ; int hw = p % HWSZ;
    int h = hw / WW, w = hw % WW;
    int row = ((h & 1) << 7) + (h >> 1);
    long base  = (long)b*CCH*HWSZ + hw;
    long baseS = (long)b*CCH*HWSZ + (long)row*WW + w;
    float xc[28];
#pragma unroll
    for (int c=0;c<28;c++) xc[c] = g_xconv[base + (long)c*HWSZ];
    float cf = coef[hw];
#pragma unroll 2
    for (int o=0;o<28;o++){
        float s = 0.f;
#pragma unroll
        for (int c=0;c<28;c++) s += Ws[o*28+c]*xc[c];
        float th = gelu_f(s) + xc[o];
        long off = base + (long)o*HWSZ;
        g_xn[baseS + (long)o*HWSZ] = cf*g_xlow[off] + (1.0f-cf)*th + g_xdct[off];
    }
}

// ---------------- fusion (with on-the-fly pass4 output butterfly) --------------
__global__ __launch_bounds__(256) void fusion_kernel(
    const float* __restrict__ fw, const float* __restrict__ fb,
    float* __restrict__ out)
{
    __shared__ float Ws[28*56];
    __shared__ float fbs[28];
    __shared__ float so[256*28];
    for (int idx = threadIdx.x; idx < 28*56; idx += 256) Ws[idx] = fw[idx];
    if (threadIdx.x < 28) fbs[threadIdx.x] = fb[threadIdx.x];
    __syncthreads();
    int p = blockIdx.x*256 + threadIdx.x;
    int b = p / HWSZ; int hw = p % HWSZ;
    int h = hw / WW, w = hw % WW;
    int wc   = (w < 160) ? w : (319 - w);
    float sg = (w < 160) ? 1.0f : -1.0f;
    long base  = (long)b*CCH*HWSZ + hw;
    long baseY = (long)b*CCH*HWSZ + (long)h*WW + wc;
    float fd[28], lc[28];
#pragma unroll
    for (int c=0;c<28;c++){
        long o = baseY + (long)c*HWSZ;
        fd[c] = g_tmp[o] + sg*g_tmp[o + 160];
        lc[c] = g_loc[base + (long)c*HWSZ];
    }
#pragma unroll 2
    for (int o=0;o<28;o++){
        float s = fbs[o];
#pragma unroll
        for (int c=0;c<28;c++) s += Ws[o*56 + c]*fd[c] + Ws[o*56 + 28 + c]*lc[c];
        so[threadIdx.x*28 + o] = s;
    }
    __syncthreads();
    long obase = (long)blockIdx.x*256*28;
    for (int idx = threadIdx.x; idx < 256*28; idx += 256) out[obase + idx] = so[idx];
}

// ---------------- launch -------------------------------------------------------
extern "C" void kernel_launch(void* const* d_in, const int* in_sizes, int n_in,
                              void* d_out, int out_size)
{
    const float* x          = (const float*)d_in[0];
    const float* spec_wq    = (const float*)d_in[1];
    const float* spec_wk    = (const float*)d_in[2];
    const float* spec_wv    = (const float*)d_in[3];
    const float* spec_rs    = (const float*)d_in[4];
    const float* spec_pw    = (const float*)d_in[5];
    const float* spec_pb    = (const float*)d_in[6];
    const float* hf1_pw_w   = (const float*)d_in[7];
    const float* hf1_dw_w   = (const float*)d_in[8];
    const float* hf2_pw_w   = (const float*)d_in[9];
    const float* coef_emb   = (const float*)d_in[10];
    const float* loc_wq     = (const float*)d_in[11];
    const float* loc_wkv    = (const float*)d_in[12];
    const float* loc_pos    = (const float*)d_in[13];
    const float* loc_pw     = (const float*)d_in[14];
    const float* loc_pb     = (const float*)d_in[15];
    const float* fus_w      = (const float*)d_in[16];
    const float* fus_b      = (const float*)d_in[17];
    float* out = (float*)d_out;

    float *p_xn, *p_tmp, *p_b1, *p_xdct;
    float *p_DHp, *p_DWp, *p_DIHp, *p_DIWp;
    cudaGetSymbolAddress((void**)&p_xn,   g_xn);
    cudaGetSymbolAddress((void**)&p_tmp,  g_tmp);
    cudaGetSymbolAddress((void**)&p_b1,   g_b1);
    cudaGetSymbolAddress((void**)&p_xdct, g_xdct);
    cudaGetSymbolAddress((void**)&p_DHp,  g_DHp);
    cudaGetSymbolAddress((void**)&p_DWp,  g_DWp);
    cudaGetSymbolAddress((void**)&p_DIHp, g_DIHp);
    cudaGetSymbolAddress((void**)&p_DIWp, g_DIWp);

    const int LOCAL_SMEM = 13152 * 4;
    cudaFuncSetAttribute(local_attn_kernel, cudaFuncAttributeMaxDynamicSharedMemorySize, LOCAL_SMEM);

    // packed DCT matrices
    fill_DHp <<<128, 256>>>(p_DHp);
    fill_DWp <<<200, 256>>>(p_DWp);
    fill_DIHp<<<128, 256>>>(p_DIHp);
    fill_DIWp<<<200, 256>>>(p_DIWp);

    // NHWC -> NCHW
    transpose_in<<<NB*(HWSZ/32), 256>>>(x);

    // ---- forward DCT (halved) ----
    bf_h<<<8960, 256>>>();
    gemm_n<<<dim3(5,2,112), 256>>>(p_DHp, 128, 128*128,
                                   p_b1, 320, HWSZ, (long)128*320,
                                   p_tmp, 320, HWSZ, 320, 2, 128);
    bf_w<<<8960, 256>>>();
    gemm_t<<<dim3(5,4,112), 256>>>(p_b1, 320, HWSZ, 160,
                                   p_DWp, 160, (long)160*160,
                                   p_xdct, 320, HWSZ, 1, 2, 160);

    // spectral attention -> g_xlow
    spec_attn_kernel<<<2560, 256>>>(spec_wq, spec_wk, spec_wv,
                                    spec_rs, spec_pw, spec_pb);

    // high-frequency path; combine writes parity-split-row xo into g_xn
    pw1_gelu_kernel<<<NPIX/256, 256>>>(hf1_pw_w);
    dw_gelu_add_kernel<<<(NELEM+255)/256, 256>>>(hf1_dw_w);
    combine_kernel<<<NPIX/256, 256>>>(hf2_pw_w, coef_emb);

    // ---- inverse DCT (halved) ----
    gemm_n<<<dim3(5,2,112), 256>>>(p_DIHp, 128, 128*128,
                                   p_xn, 320, HWSZ, (long)128*320,
                                   p_tmp, 320, HWSZ, (long)128*320, 1, 128);
    bf_mid<<<8960, 256>>>();
    gemm_t<<<dim3(5,4,112), 256>>>(p_b1, 320, HWSZ, 160,
                                   p_DIWp, 160, (long)160*160,
                                   p_tmp, 320, HWSZ, 160, 1, 160);

    // local attention -> g_loc
    loc_fuse_kernel<<<(12544+255)/256, 256>>>(loc_wq, loc_wkv, loc_pw);
    local_attn_kernel<<<2560, 256, LOCAL_SMEM>>>(x, loc_pos, loc_pb);

    // fusion (includes pass4 output butterfly) -> NHWC output
    fusion_kernel<<<NPIX/256, 256>>>(fus_w, fus_b, out);
}